// round 12
// baseline (speedup 1.0000x reference)
#include <cuda_runtime.h>
#include <cuda_bf16.h>
#include <math.h>
#include <stdint.h>

// ---------------- problem constants ----------------
#define NT    16384
#define DD    512
#define FFD   2048
#define NH    8
#define NL    4
#define NTAG  11
#define SB    64
#define SS    256
#define START_TAG 9
#define STOP_TAG  10
#define SQRT_D 22.627416997969522f

// weight bf16 pool offsets (elements)
#define OFF_QKV 0u
#define CNT_QKV (4u * 1536u * 512u)
#define OFF_WO  (OFF_QKV + CNT_QKV)
#define CNT_WO  (4u * 512u * 512u)
#define OFF_W1  (OFF_WO + CNT_WO)
#define CNT_W1  (4u * 2048u * 512u)
#define OFF_W2  (OFF_W1 + CNT_W1)
#define CNT_W2  (4u * 512u * 2048u)
#define WB_TOTAL (OFF_W2 + CNT_W2)

// ---------------- scratch ----------------
__device__ float         g_x  [NT * DD];
__device__ __nv_bfloat16 g_xb [NT * DD];
__device__ __nv_bfloat16 g_qkvb[NT * 3 * DD];
__device__ __nv_bfloat16 g_attb[NT * DD];
__device__ float         g_o  [NT * DD];
__device__ __nv_bfloat16 g_hb [NT * FFD];
__device__ float         g_pe [SS * DD];
__device__ float         g_em [NT * NTAG];
__device__ float         g_loss[SB];
__device__ __nv_bfloat16 g_wb [WB_TOTAL];

__device__ __forceinline__ uint32_t smem_to_u32(const void* p) {
    uint32_t a;
    asm("{ .reg .u64 t; cvta.to.shared.u64 t, %1; cvt.u32.u64 %0, t; }" : "=r"(a) : "l"(p));
    return a;
}

// ---------------- all weights fp32 -> bf16 in ONE launch ----------------
__global__ void wconv_all(const float* __restrict__ Wqkv, const float* __restrict__ Wo,
                          const float* __restrict__ W1, const float* __restrict__ W2) {
    const unsigned C0 = CNT_QKV / 2, C1 = CNT_WO / 2, C2 = CNT_W1 / 2;
    unsigned i = blockIdx.x * blockDim.x + threadIdx.x;
    const float2* src;
    unsigned j;
    if (i < C0)                { src = (const float2*)Wqkv; j = i; }
    else if (i < C0 + C1)      { src = (const float2*)Wo;   j = i - C0; }
    else if (i < C0 + C1 + C2) { src = (const float2*)W1;   j = i - C0 - C1; }
    else                       { src = (const float2*)W2;   j = i - C0 - C1 - C2; }
    float2 f = src[j];
    ((__nv_bfloat162*)g_wb)[i] = __floats2bfloat162_rn(f.x, f.y);
}

// ---------------- positional encoding ----------------
__global__ void pe_kernel() {
    int s = blockIdx.x;
    int i = threadIdx.x;
    double div = exp((double)(2 * i) * (-9.210340371976184 / 512.0));
    double sv, cv;
    sincos((double)s * div, &sv, &cv);
    g_pe[s * DD + 2 * i]     = (float)sv;
    g_pe[s * DD + 2 * i + 1] = (float)cv;
}

// ---------------- embedding + PE (fp32 + bf16 mirror) ----------------
__global__ void embed_kernel(const float* __restrict__ emb, const int* __restrict__ sent) {
    int n = blockIdx.x;
    int s = n & (SS - 1);
    int tok = sent[n];
    int d = threadIdx.x * 2;
    float2 e = *(const float2*)(emb + (size_t)tok * DD + d);
    float2 p = *(const float2*)(g_pe + s * DD + d);
    float2 r;
    r.x = e.x * SQRT_D + p.x;
    r.y = e.y * SQRT_D + p.y;
    *(float2*)(g_x + (size_t)n * DD + d) = r;
    *(__nv_bfloat162*)(g_xb + (size_t)n * DD + d) = __floats2bfloat162_rn(r.x, r.y);
}

// ---------------- mma.sync primitives ----------------
__device__ __forceinline__ void cp16(uint32_t saddr, const void* gaddr) {
    asm volatile("cp.async.cg.shared.global [%0], [%1], 16;\n" :: "r"(saddr), "l"(gaddr));
}
__device__ __forceinline__ void ldm_x4(uint32_t* r, uint32_t addr) {
    asm volatile("ldmatrix.sync.aligned.m8n8.x4.shared.b16 {%0,%1,%2,%3}, [%4];\n"
                 : "=r"(r[0]), "=r"(r[1]), "=r"(r[2]), "=r"(r[3]) : "r"(addr));
}
__device__ __forceinline__ void ldm_x4t(uint32_t* r, uint32_t addr) {
    asm volatile("ldmatrix.sync.aligned.m8n8.x4.trans.shared.b16 {%0,%1,%2,%3}, [%4];\n"
                 : "=r"(r[0]), "=r"(r[1]), "=r"(r[2]), "=r"(r[3]) : "r"(addr));
}
__device__ __forceinline__ void mma16816(float* c, const uint32_t* a, const uint32_t* b) {
    asm volatile(
        "mma.sync.aligned.m16n8k16.row.col.f32.bf16.bf16.f32 "
        "{%0,%1,%2,%3}, {%4,%5,%6,%7}, {%8,%9}, {%0,%1,%2,%3};\n"
        : "+f"(c[0]), "+f"(c[1]), "+f"(c[2]), "+f"(c[3])
        : "r"(a[0]), "r"(a[1]), "r"(a[2]), "r"(a[3]), "r"(b[0]), "r"(b[1]));
}
__device__ __forceinline__ uint32_t packbf(float x, float y) {
    __nv_bfloat162 t = __floats2bfloat162_rn(x, y);
    return *(uint32_t*)&t;
}

// ============ bf16 HMMA GEMM: C[M,N] = A[M,K] @ W[N,K]^T + bias ============
// SEL 0: A=g_xb  -> g_qkvb (bf16)      N=1536 K=512
// SEL 1: A=g_attb-> g_o    (f32)       N=512  K=512
// SEL 2: A=g_xb  -> g_hb   (bf16,relu) N=2048 K=512
// SEL 3: A=g_hb  -> g_o    (f32)       N=512  K=2048
// 128x128 tile, k-chunk 64, 256 thr (2x4 warps of 64x32), 3-stage cp.async,
// fragment double-buffer across k16 steps (hides LDSM latency).
#define SA 72                        // padded smem row stride (bf16); 144B
#define GSTG (256 * SA * 2)          // 36864 B per stage
#define GEMM_SMEM (3 * GSTG)         // 110592 B

template<int SEL>
__global__ __launch_bounds__(256) void mma_gemm(unsigned woff, const float* __restrict__ bias) {
    constexpr int  K       = (SEL == 3) ? 2048 : 512;
    constexpr int  Nn      = (SEL == 0) ? 1536 : (SEL == 2) ? 2048 : 512;
    constexpr int  KB      = K / 64;
    constexpr bool RELU    = (SEL == 2);
    constexpr bool BF16OUT = (SEL == 0) || (SEL == 2);

    const __nv_bfloat16* A = (SEL == 1) ? g_attb : (SEL == 3) ? g_hb : g_xb;
    const __nv_bfloat16* W = g_wb + woff;

    extern __shared__ char dsm[];
    const uint32_t smb = smem_to_u32(dsm);

    const int tid    = threadIdx.x;
    const int lane   = tid & 31;
    const int wid    = tid >> 5;
    const int warp_m = wid & 1;
    const int warp_n = wid >> 1;
    const int row0   = blockIdx.y * 128;
    const int col0   = blockIdx.x * 128;

    // per-warp, k-independent pieces of the ldmatrix addresses
    const int a_row = warp_m * 64 + (lane & 7) + ((lane >> 3) & 1) * 8;  // + mt*16
    const int a_col = (lane >> 4) * 8;                                    // + k16
    const int bg    = lane >> 3;
    const int b_row = 128 + warp_n * 32 + (bg >> 1) * 8 + (lane & 7);     // + bt*16
    const int b_col = (bg & 1) * 8;                                       // + k16

    float acc[4][4][4];
    #pragma unroll
    for (int mt = 0; mt < 4; mt++)
        #pragma unroll
        for (int nt = 0; nt < 4; nt++)
            #pragma unroll
            for (int q = 0; q < 4; q++) acc[mt][nt][q] = 0.f;

    // load one 64-wide k-chunk: rows 0..127 = A, 128..255 = W; 8 chunks of 16B per row
    auto load_tiles = [&](int s, int k0) {
        uint32_t base = smb + (uint32_t)s * GSTG;
        #pragma unroll
        for (int i = 0; i < 8; i++) {
            int idx = i * 256 + tid;          // 0..2047
            int r   = idx >> 3;               // 0..255
            int ch  = idx & 7;                // 0..7
            uint32_t so = base + (uint32_t)(r * SA + ch * 8) * 2;
            const __nv_bfloat16* g = (r < 128)
                ? A + (size_t)(row0 + r) * K + k0 + ch * 8
                : W + (size_t)(col0 + (r - 128)) * K + k0 + ch * 8;
            cp16(so, g);
        }
        asm volatile("cp.async.commit_group;\n" ::: "memory");
    };

    load_tiles(0, 0);
    load_tiles(1, 64);

    for (int kb = 0; kb < KB; kb++) {
        if (kb + 2 < KB) load_tiles((kb + 2) % 3, (kb + 2) * 64);
        else             asm volatile("cp.async.commit_group;\n" ::: "memory");
        asm volatile("cp.async.wait_group 2;\n" ::: "memory");
        __syncthreads();

        const uint32_t bufb = smb + (uint32_t)(kb % 3) * GSTG;

        // fragment double-buffer: load ks+1 while MMAing ks
        uint32_t af[2][4][4];
        uint32_t bf[2][2][4];

        // prime ks = 0
        #pragma unroll
        for (int mt = 0; mt < 4; mt++)
            ldm_x4(af[0][mt], bufb + (uint32_t)((a_row + mt * 16) * SA + a_col) * 2);
        #pragma unroll
        for (int bt = 0; bt < 2; bt++)
            ldm_x4(bf[0][bt], bufb + (uint32_t)((b_row + bt * 16) * SA + b_col) * 2);

        #pragma unroll
        for (int ks = 0; ks < 4; ks++) {
            const int cur = ks & 1;
            const int nxt = cur ^ 1;
            if (ks < 3) {
                const int k16 = (ks + 1) * 16;
                #pragma unroll
                for (int mt = 0; mt < 4; mt++)
                    ldm_x4(af[nxt][mt],
                           bufb + (uint32_t)((a_row + mt * 16) * SA + a_col + k16) * 2);
                #pragma unroll
                for (int bt = 0; bt < 2; bt++)
                    ldm_x4(bf[nxt][bt],
                           bufb + (uint32_t)((b_row + bt * 16) * SA + b_col + k16) * 2);
            }
            #pragma unroll
            for (int mt = 0; mt < 4; mt++)
                #pragma unroll
                for (int nt = 0; nt < 4; nt++)
                    mma16816(acc[mt][nt], af[cur][mt], &bf[cur][nt >> 1][(nt & 1) * 2]);
        }
        __syncthreads();
    }

    #pragma unroll
    for (int mt = 0; mt < 4; mt++) {
        int row = row0 + warp_m * 64 + mt * 16 + (lane >> 2);
        #pragma unroll
        for (int nt = 0; nt < 4; nt++) {
            int col = col0 + warp_n * 32 + nt * 8 + (lane & 3) * 2;
            float bx = bias[col], by = bias[col + 1];
            float v0 = acc[mt][nt][0] + bx, v1 = acc[mt][nt][1] + by;
            float v2 = acc[mt][nt][2] + bx, v3 = acc[mt][nt][3] + by;
            if (RELU) {
                v0 = fmaxf(v0, 0.f); v1 = fmaxf(v1, 0.f);
                v2 = fmaxf(v2, 0.f); v3 = fmaxf(v3, 0.f);
            }
            if (BF16OUT) {
                __nv_bfloat16* D = (SEL == 0) ? g_qkvb : g_hb;
                *(__nv_bfloat162*)(D + (size_t)row * Nn + col) =
                    __floats2bfloat162_rn(v0, v1);
                *(__nv_bfloat162*)(D + (size_t)(row + 8) * Nn + col) =
                    __floats2bfloat162_rn(v2, v3);
            } else {
                *(float2*)(g_o + (size_t)row * Nn + col)       = make_float2(v0, v1);
                *(float2*)(g_o + (size_t)(row + 8) * Nn + col) = make_float2(v2, v3);
            }
        }
    }
}

// ============ flash attention: block per (b,h), 8 warps x 32 q-rows, bf16 HMMA ============
#define SV 72
#define ATTN_SMEM (3 * 256 * SV * 2)

__global__ __launch_bounds__(256) void attn_kernel() {
    extern __shared__ __nv_bfloat16 asmem[];
    __nv_bfloat16* Qs = asmem;
    __nv_bfloat16* Ks = asmem + 256 * SV;
    __nv_bfloat16* Vs = asmem + 2 * 256 * SV;
    const uint32_t q32 = smem_to_u32(Qs);
    const uint32_t k32 = smem_to_u32(Ks);
    const uint32_t v32 = smem_to_u32(Vs);

    const int bh = blockIdx.x;
    const int b  = bh >> 3;
    const int h  = bh & 7;
    const int tid  = threadIdx.x;
    const int lane = tid & 31;
    const int wid  = tid >> 5;

    const __nv_bfloat16* base = g_qkvb + (size_t)b * SS * 1536 + h * 64;

    #pragma unroll
    for (int i = 0; i < 8; i++) {
        int c   = i * 256 + tid;
        int r   = c >> 3;
        int seg = (c & 7) * 8;
        const __nv_bfloat16* rowp = base + (size_t)r * 1536;
        uint32_t so = (uint32_t)(r * SV + seg) * 2;
        cp16(q32 + so, rowp + seg);
        cp16(k32 + so, rowp + 512 + seg);
        cp16(v32 + so, rowp + 1024 + seg);
    }
    asm volatile("cp.async.commit_group;\ncp.async.wait_group 0;\n" ::: "memory");
    __syncthreads();

    const int qr0 = wid * 32;

    float mrun[2][2], lrun[2][2], oacc[2][8][4];
    #pragma unroll
    for (int mt = 0; mt < 2; mt++) {
        mrun[mt][0] = mrun[mt][1] = -1e30f;
        lrun[mt][0] = lrun[mt][1] = 0.f;
        #pragma unroll
        for (int n8 = 0; n8 < 8; n8++)
            #pragma unroll
            for (int q = 0; q < 4; q++) oacc[mt][n8][q] = 0.f;
    }

    for (int kc = 0; kc < 4; kc++) {
        float sacc[2][8][4];
        #pragma unroll
        for (int mt = 0; mt < 2; mt++)
            #pragma unroll
            for (int n8 = 0; n8 < 8; n8++)
                #pragma unroll
                for (int q = 0; q < 4; q++) sacc[mt][n8][q] = 0.f;

        #pragma unroll
        for (int ks = 0; ks < 4; ks++) {
            const int k16 = ks * 16;
            uint32_t af[2][4];
            #pragma unroll
            for (int mt = 0; mt < 2; mt++) {
                int r = qr0 + mt * 16 + (lane & 7) + ((lane >> 3) & 1) * 8;
                int c = k16 + (lane >> 4) * 8;
                ldm_x4(af[mt], q32 + (uint32_t)(r * SV + c) * 2);
            }
            uint32_t kf[4][4];
            #pragma unroll
            for (int bt = 0; bt < 4; bt++) {
                int g = lane >> 3;
                int r = kc * 64 + bt * 16 + (g >> 1) * 8 + (lane & 7);
                int c = k16 + (g & 1) * 8;
                ldm_x4(kf[bt], k32 + (uint32_t)(r * SV + c) * 2);
            }
            #pragma unroll
            for (int mt = 0; mt < 2; mt++)
                #pragma unroll
                for (int n8 = 0; n8 < 8; n8++)
                    mma16816(sacc[mt][n8], af[mt], &kf[n8 >> 1][(n8 & 1) * 2]);
        }

        #pragma unroll
        for (int mt = 0; mt < 2; mt++)
            #pragma unroll
            for (int n8 = 0; n8 < 8; n8++)
                #pragma unroll
                for (int q = 0; q < 4; q++) sacc[mt][n8][q] *= 0.125f;

        #pragma unroll
        for (int mt = 0; mt < 2; mt++) {
            #pragma unroll
            for (int h2 = 0; h2 < 2; h2++) {
                float vmax = -1e30f;
                #pragma unroll
                for (int n8 = 0; n8 < 8; n8++)
                    vmax = fmaxf(vmax, fmaxf(sacc[mt][n8][h2 * 2], sacc[mt][n8][h2 * 2 + 1]));
                vmax = fmaxf(vmax, __shfl_xor_sync(0xffffffffu, vmax, 1));
                vmax = fmaxf(vmax, __shfl_xor_sync(0xffffffffu, vmax, 2));
                float mold = mrun[mt][h2];
                float mnew = fmaxf(mold, vmax);
                float alpha = __expf(mold - mnew);
                float pssum = 0.f;
                #pragma unroll
                for (int n8 = 0; n8 < 8; n8++) {
                    float p0 = __expf(sacc[mt][n8][h2 * 2]     - mnew);
                    float p1 = __expf(sacc[mt][n8][h2 * 2 + 1] - mnew);
                    sacc[mt][n8][h2 * 2]     = p0;
                    sacc[mt][n8][h2 * 2 + 1] = p1;
                    pssum += p0 + p1;
                }
                pssum += __shfl_xor_sync(0xffffffffu, pssum, 1);
                pssum += __shfl_xor_sync(0xffffffffu, pssum, 2);
                lrun[mt][h2] = lrun[mt][h2] * alpha + pssum;
                mrun[mt][h2] = mnew;
                #pragma unroll
                for (int n8 = 0; n8 < 8; n8++) {
                    oacc[mt][n8][h2 * 2]     *= alpha;
                    oacc[mt][n8][h2 * 2 + 1] *= alpha;
                }
            }
        }

        #pragma unroll
        for (int ks = 0; ks < 4; ks++) {
            uint32_t pf[2][4];
            #pragma unroll
            for (int mt = 0; mt < 2; mt++) {
                const float* s0 = sacc[mt][ks * 2];
                const float* s1 = sacc[mt][ks * 2 + 1];
                pf[mt][0] = packbf(s0[0], s0[1]);
                pf[mt][1] = packbf(s0[2], s0[3]);
                pf[mt][2] = packbf(s1[0], s1[1]);
                pf[mt][3] = packbf(s1[2], s1[3]);
            }
            uint32_t vf[4][4];
            #pragma unroll
            for (int bt = 0; bt < 4; bt++) {
                int g = lane >> 3;
                int kr = kc * 64 + ks * 16 + (g & 1) * 8 + (lane & 7);
                int nc = bt * 16 + (g >> 1) * 8;
                ldm_x4t(vf[bt], v32 + (uint32_t)(kr * SV + nc) * 2);
            }
            #pragma unroll
            for (int mt = 0; mt < 2; mt++)
                #pragma unroll
                for (int n8 = 0; n8 < 8; n8++)
                    mma16816(oacc[mt][n8], pf[mt], &vf[n8 >> 1][(n8 & 1) * 2]);
        }
    }

    #pragma unroll
    for (int mt = 0; mt < 2; mt++) {
        #pragma unroll
        for (int h2 = 0; h2 < 2; h2++) {
            int row = qr0 + mt * 16 + (lane >> 2) + h2 * 8;
            float inv = 1.f / lrun[mt][h2];
            __nv_bfloat16* op = g_attb + (size_t)(b * SS + row) * DD + h * 64;
            #pragma unroll
            for (int n8 = 0; n8 < 8; n8++) {
                int col = n8 * 8 + (lane & 3) * 2;
                *(__nv_bfloat162*)(op + col) =
                    __floats2bfloat162_rn(oacc[mt][n8][h2 * 2] * inv,
                                          oacc[mt][n8][h2 * 2 + 1] * inv);
            }
        }
    }
}

// ---------------- fused residual add + LN (warp/token, fp32 + bf16 mirror) --------
__global__ void add_ln_kernel(const float* __restrict__ g, const float* __restrict__ bta) {
    int gw   = (blockIdx.x * blockDim.x + threadIdx.x) >> 5;
    int lane = threadIdx.x & 31;
    float* xp = g_x + (size_t)gw * DD;
    __nv_bfloat16* xbp = g_xb + (size_t)gw * DD;
    const float* rp = g_o + (size_t)gw * DD;

    float v[16];
    float s = 0.f;
    #pragma unroll
    for (int i = 0; i < 4; i++) {
        float4 a = *(const float4*)(xp + i * 128 + lane * 4);
        float4 c = *(const float4*)(rp + i * 128 + lane * 4);
        v[i * 4]     = a.x + c.x; v[i * 4 + 1] = a.y + c.y;
        v[i * 4 + 2] = a.z + c.z; v[i * 4 + 3] = a.w + c.w;
        s += v[i * 4] + v[i * 4 + 1] + v[i * 4 + 2] + v[i * 4 + 3];
    }
    #pragma unroll
    for (int o = 16; o; o >>= 1) s += __shfl_xor_sync(0xffffffffu, s, o);
    float mean = s * (1.f / 512.f);
    float vs = 0.f;
    #pragma unroll
    for (int i = 0; i < 16; i++) { float d = v[i] - mean; vs += d * d; }
    #pragma unroll
    for (int o = 16; o; o >>= 1) vs += __shfl_xor_sync(0xffffffffu, vs, o);
    float rstd = rsqrtf(vs * (1.f / 512.f) + 1e-5f);
    #pragma unroll
    for (int i = 0; i < 4; i++) {
        float4 gg = *(const float4*)(g + i * 128 + lane * 4);
        float4 bb = *(const float4*)(bta + i * 128 + lane * 4);
        float4 o4;
        o4.x = (v[i * 4]     - mean) * rstd * gg.x + bb.x;
        o4.y = (v[i * 4 + 1] - mean) * rstd * gg.y + bb.y;
        o4.z = (v[i * 4 + 2] - mean) * rstd * gg.z + bb.z;
        o4.w = (v[i * 4 + 3] - mean) * rstd * gg.w + bb.w;
        *(float4*)(xp + i * 128 + lane * 4) = o4;
        __nv_bfloat162 b0 = __floats2bfloat162_rn(o4.x, o4.y);
        __nv_bfloat162 b1 = __floats2bfloat162_rn(o4.z, o4.w);
        uint2 pk = make_uint2(*(uint32_t*)&b0, *(uint32_t*)&b1);
        *(uint2*)(xbp + i * 128 + lane * 4) = pk;
    }
}

// ---------------- emissions: warp per token ----------------
__global__ void emis_kernel(const float* __restrict__ Wt, const float* __restrict__ bt) {
    int gw   = (blockIdx.x * blockDim.x + threadIdx.x) >> 5;
    int lane = threadIdx.x & 31;
    const float* xp = g_x + (size_t)gw * DD;
    float xv[16];
    #pragma unroll
    for (int i = 0; i < 16; i++) xv[i] = xp[i * 32 + lane];
    #pragma unroll
    for (int t = 0; t < NTAG; t++) {
        const float* wp = Wt + t * DD;
        float s = 0.f;
        #pragma unroll
        for (int i = 0; i < 16; i++) s += xv[i] * wp[i * 32 + lane];
        #pragma unroll
        for (int o = 16; o; o >>= 1) s += __shfl_xor_sync(0xffffffffu, s, o);
        if (lane == 0) g_em[(size_t)gw * NTAG + t] = s + bt[t];
    }
}

// ---------------- CRF: one warp per batch element ----------------
__global__ void crf_kernel(const float* __restrict__ trans, const int* __restrict__ tags) {
    int b    = blockIdx.x;
    int lane = threadIdx.x;
    __shared__ float trs[NTAG * NTAG];
    __shared__ float las[16];
    for (int i = lane; i < NTAG * NTAG; i += 32) trs[i] = trans[i];
    __syncwarp();

    const float* eb = g_em + (size_t)b * SS * NTAG;
    const int*   tg = tags + b * SS;

    float ts = 0.f;
    for (int s = lane; s < SS; s += 32) {
        int cur  = tg[s];
        int prev = (s == 0) ? START_TAG : tg[s - 1];
        ts += eb[s * NTAG + cur] + trs[prev * NTAG + cur];
    }
    #pragma unroll
    for (int o = 16; o; o >>= 1) ts += __shfl_xor_sync(0xffffffffu, ts, o);

    if (lane < NTAG) las[lane] = (lane == START_TAG) ? 0.f : -10000.f;
    __syncwarp();
    for (int s = 0; s < SS; s++) {
        float nla = -1e30f;
        if (lane < NTAG) {
            float m = -1e30f;
            #pragma unroll
            for (int i = 0; i < NTAG; i++) m = fmaxf(m, las[i] + trs[i * NTAG + lane]);
            float sme = 0.f;
            #pragma unroll
            for (int i = 0; i < NTAG; i++) sme += __expf(las[i] + trs[i * NTAG + lane] - m);
            nla = m + __logf(sme) + eb[s * NTAG + lane];
        }
        __syncwarp();
        if (lane < NTAG) las[lane] = nla;
        __syncwarp();
    }
    float v = (lane < NTAG) ? (las[lane] + trs[lane * NTAG + STOP_TAG]) : -1e30f;
    float m = v;
    #pragma unroll
    for (int o = 16; o; o >>= 1) m = fmaxf(m, __shfl_xor_sync(0xffffffffu, m, o));
    float sme = __expf(v - m);
    #pragma unroll
    for (int o = 16; o; o >>= 1) sme += __shfl_xor_sync(0xffffffffu, sme, o);
    if (lane == 0) {
        float logZ = m + __logf(sme);
        float last = trs[tg[SS - 1] * NTAG + STOP_TAG];
        g_loss[b] = logZ - (ts + last);
    }
}

__global__ void loss_reduce(float* __restrict__ out) {
    if (threadIdx.x == 0) {
        float s = 0.f;
        for (int i = 0; i < SB; i++) s += g_loss[i];
        out[0] = s * (1.f / SB);
    }
}

// ---------------- launch ----------------
extern "C" void kernel_launch(void* const* d_in, const int* in_sizes, int n_in,
                              void* d_out, int out_size) {
    const float* Wqkv  = (const float*)d_in[1];
    const float* bqkv  = (const float*)d_in[2];
    const float* Wo    = (const float*)d_in[3];
    const float* bo    = (const float*)d_in[4];
    const float* W1    = (const float*)d_in[5];
    const float* b1    = (const float*)d_in[6];
    const float* W2    = (const float*)d_in[7];
    const float* b2    = (const float*)d_in[8];
    const float* ln1g  = (const float*)d_in[9];
    const float* ln1b  = (const float*)d_in[10];
    const float* ln2g  = (const float*)d_in[11];
    const float* ln2b  = (const float*)d_in[12];
    const float* Wtag  = (const float*)d_in[13];
    const float* btag  = (const float*)d_in[14];
    const float* trans = (const float*)d_in[15];
    const int*   sent  = (const int*)d_in[16];
    const int*   tags  = (const int*)d_in[17];
    float* out = (float*)d_out;

    cudaFuncSetAttribute(attn_kernel, cudaFuncAttributeMaxDynamicSharedMemorySize, ATTN_SMEM);
    cudaFuncSetAttribute(mma_gemm<0>, cudaFuncAttributeMaxDynamicSharedMemorySize, GEMM_SMEM);
    cudaFuncSetAttribute(mma_gemm<1>, cudaFuncAttributeMaxDynamicSharedMemorySize, GEMM_SMEM);
    cudaFuncSetAttribute(mma_gemm<2>, cudaFuncAttributeMaxDynamicSharedMemorySize, GEMM_SMEM);
    cudaFuncSetAttribute(mma_gemm<3>, cudaFuncAttributeMaxDynamicSharedMemorySize, GEMM_SMEM);

    wconv_all<<<(WB_TOTAL / 2 + 255) / 256, 256>>>(Wqkv, Wo, W1, W2);
    pe_kernel<<<SS, DD / 2>>>();
    embed_kernel<<<NT, DD / 2>>>((const float*)d_in[0], sent);

    for (int l = 0; l < NL; l++) {
        mma_gemm<0><<<dim3(1536 / 128, NT / 128), 256, GEMM_SMEM>>>(
            OFF_QKV + (unsigned)l * 1536u * 512u, bqkv + (size_t)l * 1536);
        attn_kernel<<<SB * NH, 256, ATTN_SMEM>>>();
        mma_gemm<1><<<dim3(512 / 128, NT / 128), 256, GEMM_SMEM>>>(
            OFF_WO + (unsigned)l * 512u * 512u, bo + (size_t)l * 512);
        add_ln_kernel<<<NT / 8, 256>>>(ln1g + (size_t)l * DD, ln1b + (size_t)l * DD);
        mma_gemm<2><<<dim3(2048 / 128, NT / 128), 256, GEMM_SMEM>>>(
            OFF_W1 + (unsigned)l * 2048u * 512u, b1 + (size_t)l * 2048);
        mma_gemm<3><<<dim3(512 / 128, NT / 128), 256, GEMM_SMEM>>>(
            OFF_W2 + (unsigned)l * 512u * 2048u, b2 + (size_t)l * 512);
        add_ln_kernel<<<NT / 8, 256>>>(ln2g + (size_t)l * DD, ln2b + (size_t)l * DD);
    }

    emis_kernel<<<NT / 8, 256>>>(Wtag, btag);
    crf_kernel<<<SB, 32>>>(trans, tags);
    loss_reduce<<<1, 1>>>(out);
}

// round 13
// speedup vs baseline: 1.0463x; 1.0463x over previous
#include <cuda_runtime.h>
#include <cuda_bf16.h>
#include <math.h>
#include <stdint.h>

// ---------------- problem constants ----------------
#define NT    16384
#define DD    512
#define FFD   2048
#define NH    8
#define NL    4
#define NTAG  11
#define SB    64
#define SS    256
#define START_TAG 9
#define STOP_TAG  10
#define SQRT_D 22.627416997969522f

// weight bf16 pool offsets (elements)
#define OFF_QKV 0u
#define CNT_QKV (4u * 1536u * 512u)
#define OFF_WO  (OFF_QKV + CNT_QKV)
#define CNT_WO  (4u * 512u * 512u)
#define OFF_W1  (OFF_WO + CNT_WO)
#define CNT_W1  (4u * 2048u * 512u)
#define OFF_W2  (OFF_W1 + CNT_W1)
#define CNT_W2  (4u * 512u * 2048u)
#define WB_TOTAL (OFF_W2 + CNT_W2)

// ---------------- scratch ----------------
__device__ __nv_bfloat16 g_xb [NT * DD];       // activations (bf16 only)
__device__ __nv_bfloat16 g_qkvb[NT * 3 * DD];
__device__ __nv_bfloat16 g_attb[NT * DD];
__device__ float         g_o  [NT * DD];       // GEMM fp32 output (Wo / W2)
__device__ __nv_bfloat16 g_hb [NT * FFD];
__device__ float         g_pe [SS * DD];
__device__ float         g_em [NT * NTAG];
__device__ float         g_loss[SB];
__device__ __nv_bfloat16 g_wb [WB_TOTAL];

__device__ __forceinline__ uint32_t smem_to_u32(const void* p) {
    uint32_t a;
    asm("{ .reg .u64 t; cvta.to.shared.u64 t, %1; cvt.u32.u64 %0, t; }" : "=r"(a) : "l"(p));
    return a;
}

// ---------------- all weights fp32 -> bf16 in ONE launch ----------------
__global__ void wconv_all(const float* __restrict__ Wqkv, const float* __restrict__ Wo,
                          const float* __restrict__ W1, const float* __restrict__ W2) {
    const unsigned C0 = CNT_QKV / 2, C1 = CNT_WO / 2, C2 = CNT_W1 / 2;
    unsigned i = blockIdx.x * blockDim.x + threadIdx.x;
    const float2* src;
    unsigned j;
    if (i < C0)                { src = (const float2*)Wqkv; j = i; }
    else if (i < C0 + C1)      { src = (const float2*)Wo;   j = i - C0; }
    else if (i < C0 + C1 + C2) { src = (const float2*)W1;   j = i - C0 - C1; }
    else                       { src = (const float2*)W2;   j = i - C0 - C1 - C2; }
    float2 f = src[j];
    ((__nv_bfloat162*)g_wb)[i] = __floats2bfloat162_rn(f.x, f.y);
}

// ---------------- positional encoding ----------------
__global__ void pe_kernel() {
    int s = blockIdx.x;
    int i = threadIdx.x;
    double div = exp((double)(2 * i) * (-9.210340371976184 / 512.0));
    double sv, cv;
    sincos((double)s * div, &sv, &cv);
    g_pe[s * DD + 2 * i]     = (float)sv;
    g_pe[s * DD + 2 * i + 1] = (float)cv;
}

// ---------------- embedding + PE (bf16 out) ----------------
__global__ void embed_kernel(const float* __restrict__ emb, const int* __restrict__ sent) {
    int n = blockIdx.x;
    int s = n & (SS - 1);
    int tok = sent[n];
    int d = threadIdx.x * 2;
    float2 e = *(const float2*)(emb + (size_t)tok * DD + d);
    float2 p = *(const float2*)(g_pe + s * DD + d);
    *(__nv_bfloat162*)(g_xb + (size_t)n * DD + d) =
        __floats2bfloat162_rn(e.x * SQRT_D + p.x, e.y * SQRT_D + p.y);
}

// ---------------- mma.sync primitives ----------------
__device__ __forceinline__ void cp16(uint32_t saddr, const void* gaddr) {
    asm volatile("cp.async.cg.shared.global [%0], [%1], 16;\n" :: "r"(saddr), "l"(gaddr));
}
__device__ __forceinline__ void ldm_x4(uint32_t* r, uint32_t addr) {
    asm volatile("ldmatrix.sync.aligned.m8n8.x4.shared.b16 {%0,%1,%2,%3}, [%4];\n"
                 : "=r"(r[0]), "=r"(r[1]), "=r"(r[2]), "=r"(r[3]) : "r"(addr));
}
__device__ __forceinline__ void ldm_x4t(uint32_t* r, uint32_t addr) {
    asm volatile("ldmatrix.sync.aligned.m8n8.x4.trans.shared.b16 {%0,%1,%2,%3}, [%4];\n"
                 : "=r"(r[0]), "=r"(r[1]), "=r"(r[2]), "=r"(r[3]) : "r"(addr));
}
__device__ __forceinline__ void mma16816(float* c, const uint32_t* a, const uint32_t* b) {
    asm volatile(
        "mma.sync.aligned.m16n8k16.row.col.f32.bf16.bf16.f32 "
        "{%0,%1,%2,%3}, {%4,%5,%6,%7}, {%8,%9}, {%0,%1,%2,%3};\n"
        : "+f"(c[0]), "+f"(c[1]), "+f"(c[2]), "+f"(c[3])
        : "r"(a[0]), "r"(a[1]), "r"(a[2]), "r"(a[3]), "r"(b[0]), "r"(b[1]));
}
__device__ __forceinline__ uint32_t packbf(float x, float y) {
    __nv_bfloat162 t = __floats2bfloat162_rn(x, y);
    return *(uint32_t*)&t;
}

// ============ bf16 HMMA GEMM: C[M,N] = A[M,K] @ W[N,K]^T + bias ============
// SEL 0: A=g_xb  -> g_qkvb (bf16)      N=1536 K=512
// SEL 1: A=g_attb-> g_o    (f32)       N=512  K=512
// SEL 2: A=g_xb  -> g_hb   (bf16,relu) N=2048 K=512
// SEL 3: A=g_hb  -> g_o    (f32)       N=512  K=2048
// 128x128 tile, k-chunk 64, 256 thr (2x4 warps of 64x32), 3-stage cp.async.
#define SA 72                        // padded smem row stride (bf16); 144B
#define GSTG (256 * SA * 2)          // 36864 B per stage
#define GEMM_SMEM (3 * GSTG)         // 110592 B

template<int SEL>
__global__ __launch_bounds__(256) void mma_gemm(unsigned woff, const float* __restrict__ bias) {
    constexpr int  K       = (SEL == 3) ? 2048 : 512;
    constexpr int  Nn      = (SEL == 0) ? 1536 : (SEL == 2) ? 2048 : 512;
    constexpr int  KB      = K / 64;
    constexpr bool RELU    = (SEL == 2);
    constexpr bool BF16OUT = (SEL == 0) || (SEL == 2);

    const __nv_bfloat16* A = (SEL == 1) ? g_attb : (SEL == 3) ? g_hb : g_xb;
    const __nv_bfloat16* W = g_wb + woff;

    extern __shared__ char dsm[];
    const uint32_t smb = smem_to_u32(dsm);

    const int tid    = threadIdx.x;
    const int lane   = tid & 31;
    const int wid    = tid >> 5;
    const int warp_m = wid & 1;
    const int warp_n = wid >> 1;
    const int row0   = blockIdx.y * 128;
    const int col0   = blockIdx.x * 128;

    float acc[4][4][4];
    #pragma unroll
    for (int mt = 0; mt < 4; mt++)
        #pragma unroll
        for (int nt = 0; nt < 4; nt++)
            #pragma unroll
            for (int q = 0; q < 4; q++) acc[mt][nt][q] = 0.f;

    // load one 64-wide k-chunk: rows 0..127 = A, 128..255 = W; 8 chunks of 16B per row
    auto load_tiles = [&](int s, int k0) {
        uint32_t base = smb + (uint32_t)s * GSTG;
        #pragma unroll
        for (int i = 0; i < 8; i++) {
            int idx = i * 256 + tid;          // 0..2047
            int r   = idx >> 3;               // 0..255
            int ch  = idx & 7;                // 0..7
            uint32_t so = base + (uint32_t)(r * SA + ch * 8) * 2;
            const __nv_bfloat16* g = (r < 128)
                ? A + (size_t)(row0 + r) * K + k0 + ch * 8
                : W + (size_t)(col0 + (r - 128)) * K + k0 + ch * 8;
            cp16(so, g);
        }
        asm volatile("cp.async.commit_group;\n" ::: "memory");
    };

    load_tiles(0, 0);
    load_tiles(1, 64);

    for (int kb = 0; kb < KB; kb++) {
        if (kb + 2 < KB) load_tiles((kb + 2) % 3, (kb + 2) * 64);
        else             asm volatile("cp.async.commit_group;\n" ::: "memory");
        asm volatile("cp.async.wait_group 2;\n" ::: "memory");
        __syncthreads();

        const uint32_t bufb = smb + (uint32_t)(kb % 3) * GSTG;
        #pragma unroll
        for (int ks = 0; ks < 4; ks++) {
            const int k16 = ks * 16;
            uint32_t af[4][4];
            #pragma unroll
            for (int mt = 0; mt < 4; mt++) {
                int r = warp_m * 64 + mt * 16 + (lane & 7) + ((lane >> 3) & 1) * 8;
                int c = k16 + (lane >> 4) * 8;
                ldm_x4(af[mt], bufb + (uint32_t)(r * SA + c) * 2);
            }
            uint32_t bf[2][4];
            #pragma unroll
            for (int bt = 0; bt < 2; bt++) {
                int g = lane >> 3;
                int r = 128 + warp_n * 32 + bt * 16 + (g >> 1) * 8 + (lane & 7);
                int c = k16 + (g & 1) * 8;
                ldm_x4(bf[bt], bufb + (uint32_t)(r * SA + c) * 2);
            }
            #pragma unroll
            for (int mt = 0; mt < 4; mt++)
                #pragma unroll
                for (int nt = 0; nt < 4; nt++)
                    mma16816(acc[mt][nt], af[mt], &bf[nt >> 1][(nt & 1) * 2]);
        }
        __syncthreads();
    }

    #pragma unroll
    for (int mt = 0; mt < 4; mt++) {
        int row = row0 + warp_m * 64 + mt * 16 + (lane >> 2);
        #pragma unroll
        for (int nt = 0; nt < 4; nt++) {
            int col = col0 + warp_n * 32 + nt * 8 + (lane & 3) * 2;
            float bx = bias[col], by = bias[col + 1];
            float v0 = acc[mt][nt][0] + bx, v1 = acc[mt][nt][1] + by;
            float v2 = acc[mt][nt][2] + bx, v3 = acc[mt][nt][3] + by;
            if (RELU) {
                v0 = fmaxf(v0, 0.f); v1 = fmaxf(v1, 0.f);
                v2 = fmaxf(v2, 0.f); v3 = fmaxf(v3, 0.f);
            }
            if (BF16OUT) {
                __nv_bfloat16* D = (SEL == 0) ? g_qkvb : g_hb;
                *(__nv_bfloat162*)(D + (size_t)row * Nn + col) =
                    __floats2bfloat162_rn(v0, v1);
                *(__nv_bfloat162*)(D + (size_t)(row + 8) * Nn + col) =
                    __floats2bfloat162_rn(v2, v3);
            } else {
                *(float2*)(g_o + (size_t)row * Nn + col)       = make_float2(v0, v1);
                *(float2*)(g_o + (size_t)(row + 8) * Nn + col) = make_float2(v2, v3);
            }
        }
    }
}

// ============ flash attention: block per (b,h), 8 warps x 32 q-rows, bf16 HMMA ============
#define SV 72
#define ATTN_SMEM (3 * 256 * SV * 2)

__global__ __launch_bounds__(256) void attn_kernel() {
    extern __shared__ __nv_bfloat16 asmem[];
    __nv_bfloat16* Qs = asmem;
    __nv_bfloat16* Ks = asmem + 256 * SV;
    __nv_bfloat16* Vs = asmem + 2 * 256 * SV;
    const uint32_t q32 = smem_to_u32(Qs);
    const uint32_t k32 = smem_to_u32(Ks);
    const uint32_t v32 = smem_to_u32(Vs);

    const int bh = blockIdx.x;
    const int b  = bh >> 3;
    const int h  = bh & 7;
    const int tid  = threadIdx.x;
    const int lane = tid & 31;
    const int wid  = tid >> 5;

    const __nv_bfloat16* base = g_qkvb + (size_t)b * SS * 1536 + h * 64;

    #pragma unroll
    for (int i = 0; i < 8; i++) {
        int c   = i * 256 + tid;
        int r   = c >> 3;
        int seg = (c & 7) * 8;
        const __nv_bfloat16* rowp = base + (size_t)r * 1536;
        uint32_t so = (uint32_t)(r * SV + seg) * 2;
        cp16(q32 + so, rowp + seg);
        cp16(k32 + so, rowp + 512 + seg);
        cp16(v32 + so, rowp + 1024 + seg);
    }
    asm volatile("cp.async.commit_group;\ncp.async.wait_group 0;\n" ::: "memory");
    __syncthreads();

    const int qr0 = wid * 32;

    float mrun[2][2], lrun[2][2], oacc[2][8][4];
    #pragma unroll
    for (int mt = 0; mt < 2; mt++) {
        mrun[mt][0] = mrun[mt][1] = -1e30f;
        lrun[mt][0] = lrun[mt][1] = 0.f;
        #pragma unroll
        for (int n8 = 0; n8 < 8; n8++)
            #pragma unroll
            for (int q = 0; q < 4; q++) oacc[mt][n8][q] = 0.f;
    }

    for (int kc = 0; kc < 4; kc++) {
        float sacc[2][8][4];
        #pragma unroll
        for (int mt = 0; mt < 2; mt++)
            #pragma unroll
            for (int n8 = 0; n8 < 8; n8++)
                #pragma unroll
                for (int q = 0; q < 4; q++) sacc[mt][n8][q] = 0.f;

        #pragma unroll
        for (int ks = 0; ks < 4; ks++) {
            const int k16 = ks * 16;
            uint32_t af[2][4];
            #pragma unroll
            for (int mt = 0; mt < 2; mt++) {
                int r = qr0 + mt * 16 + (lane & 7) + ((lane >> 3) & 1) * 8;
                int c = k16 + (lane >> 4) * 8;
                ldm_x4(af[mt], q32 + (uint32_t)(r * SV + c) * 2);
            }
            uint32_t kf[4][4];
            #pragma unroll
            for (int bt = 0; bt < 4; bt++) {
                int g = lane >> 3;
                int r = kc * 64 + bt * 16 + (g >> 1) * 8 + (lane & 7);
                int c = k16 + (g & 1) * 8;
                ldm_x4(kf[bt], k32 + (uint32_t)(r * SV + c) * 2);
            }
            #pragma unroll
            for (int mt = 0; mt < 2; mt++)
                #pragma unroll
                for (int n8 = 0; n8 < 8; n8++)
                    mma16816(sacc[mt][n8], af[mt], &kf[n8 >> 1][(n8 & 1) * 2]);
        }

        #pragma unroll
        for (int mt = 0; mt < 2; mt++)
            #pragma unroll
            for (int n8 = 0; n8 < 8; n8++)
                #pragma unroll
                for (int q = 0; q < 4; q++) sacc[mt][n8][q] *= 0.125f;

        #pragma unroll
        for (int mt = 0; mt < 2; mt++) {
            #pragma unroll
            for (int h2 = 0; h2 < 2; h2++) {
                float vmax = -1e30f;
                #pragma unroll
                for (int n8 = 0; n8 < 8; n8++)
                    vmax = fmaxf(vmax, fmaxf(sacc[mt][n8][h2 * 2], sacc[mt][n8][h2 * 2 + 1]));
                vmax = fmaxf(vmax, __shfl_xor_sync(0xffffffffu, vmax, 1));
                vmax = fmaxf(vmax, __shfl_xor_sync(0xffffffffu, vmax, 2));
                float mold = mrun[mt][h2];
                float mnew = fmaxf(mold, vmax);
                float alpha = __expf(mold - mnew);
                float pssum = 0.f;
                #pragma unroll
                for (int n8 = 0; n8 < 8; n8++) {
                    float p0 = __expf(sacc[mt][n8][h2 * 2]     - mnew);
                    float p1 = __expf(sacc[mt][n8][h2 * 2 + 1] - mnew);
                    sacc[mt][n8][h2 * 2]     = p0;
                    sacc[mt][n8][h2 * 2 + 1] = p1;
                    pssum += p0 + p1;
                }
                pssum += __shfl_xor_sync(0xffffffffu, pssum, 1);
                pssum += __shfl_xor_sync(0xffffffffu, pssum, 2);
                lrun[mt][h2] = lrun[mt][h2] * alpha + pssum;
                mrun[mt][h2] = mnew;
                #pragma unroll
                for (int n8 = 0; n8 < 8; n8++) {
                    oacc[mt][n8][h2 * 2]     *= alpha;
                    oacc[mt][n8][h2 * 2 + 1] *= alpha;
                }
            }
        }

        #pragma unroll
        for (int ks = 0; ks < 4; ks++) {
            uint32_t pf[2][4];
            #pragma unroll
            for (int mt = 0; mt < 2; mt++) {
                const float* s0 = sacc[mt][ks * 2];
                const float* s1 = sacc[mt][ks * 2 + 1];
                pf[mt][0] = packbf(s0[0], s0[1]);
                pf[mt][1] = packbf(s0[2], s0[3]);
                pf[mt][2] = packbf(s1[0], s1[1]);
                pf[mt][3] = packbf(s1[2], s1[3]);
            }
            uint32_t vf[4][4];
            #pragma unroll
            for (int bt = 0; bt < 4; bt++) {
                int g = lane >> 3;
                int kr = kc * 64 + ks * 16 + (g & 1) * 8 + (lane & 7);
                int nc = bt * 16 + (g >> 1) * 8;
                ldm_x4t(vf[bt], v32 + (uint32_t)(kr * SV + nc) * 2);
            }
            #pragma unroll
            for (int mt = 0; mt < 2; mt++)
                #pragma unroll
                for (int n8 = 0; n8 < 8; n8++)
                    mma16816(oacc[mt][n8], pf[mt], &vf[n8 >> 1][(n8 & 1) * 2]);
        }
    }

    #pragma unroll
    for (int mt = 0; mt < 2; mt++) {
        #pragma unroll
        for (int h2 = 0; h2 < 2; h2++) {
            int row = qr0 + mt * 16 + (lane >> 2) + h2 * 8;
            float inv = 1.f / lrun[mt][h2];
            __nv_bfloat16* op = g_attb + (size_t)(b * SS + row) * DD + h * 64;
            #pragma unroll
            for (int n8 = 0; n8 < 8; n8++) {
                int col = n8 * 8 + (lane & 3) * 2;
                *(__nv_bfloat162*)(op + col) =
                    __floats2bfloat162_rn(oacc[mt][n8][h2 * 2] * inv,
                                          oacc[mt][n8][h2 * 2 + 1] * inv);
            }
        }
    }
}

// ---------------- fused residual add + LN (warp/token; bf16 x + fp32 o -> bf16 x) ----
__global__ void add_ln_kernel(const float* __restrict__ g, const float* __restrict__ bta) {
    int gw   = (blockIdx.x * blockDim.x + threadIdx.x) >> 5;
    int lane = threadIdx.x & 31;
    __nv_bfloat16* xbp = g_xb + (size_t)gw * DD;
    const float* rp = g_o + (size_t)gw * DD;

    float v[16];
    float s = 0.f;
    #pragma unroll
    for (int i = 0; i < 4; i++) {
        uint2 xb = *(const uint2*)(xbp + i * 128 + lane * 4);
        float2 x0 = __bfloat1622float2(*(__nv_bfloat162*)&xb.x);
        float2 x1 = __bfloat1622float2(*(__nv_bfloat162*)&xb.y);
        float4 c = *(const float4*)(rp + i * 128 + lane * 4);
        v[i * 4]     = x0.x + c.x; v[i * 4 + 1] = x0.y + c.y;
        v[i * 4 + 2] = x1.x + c.z; v[i * 4 + 3] = x1.y + c.w;
        s += v[i * 4] + v[i * 4 + 1] + v[i * 4 + 2] + v[i * 4 + 3];
    }
    #pragma unroll
    for (int o = 16; o; o >>= 1) s += __shfl_xor_sync(0xffffffffu, s, o);
    float mean = s * (1.f / 512.f);
    float vs = 0.f;
    #pragma unroll
    for (int i = 0; i < 16; i++) { float d = v[i] - mean; vs += d * d; }
    #pragma unroll
    for (int o = 16; o; o >>= 1) vs += __shfl_xor_sync(0xffffffffu, vs, o);
    float rstd = rsqrtf(vs * (1.f / 512.f) + 1e-5f);
    #pragma unroll
    for (int i = 0; i < 4; i++) {
        float4 gg = *(const float4*)(g + i * 128 + lane * 4);
        float4 bb = *(const float4*)(bta + i * 128 + lane * 4);
        float y0 = (v[i * 4]     - mean) * rstd * gg.x + bb.x;
        float y1 = (v[i * 4 + 1] - mean) * rstd * gg.y + bb.y;
        float y2 = (v[i * 4 + 2] - mean) * rstd * gg.z + bb.z;
        float y3 = (v[i * 4 + 3] - mean) * rstd * gg.w + bb.w;
        uint2 pk;
        pk.x = packbf(y0, y1);
        pk.y = packbf(y2, y3);
        *(uint2*)(xbp + i * 128 + lane * 4) = pk;
    }
}

// ---------------- emissions: warp per token (bf16 x) ----------------
__global__ void emis_kernel(const float* __restrict__ Wt, const float* __restrict__ bt) {
    int gw   = (blockIdx.x * blockDim.x + threadIdx.x) >> 5;
    int lane = threadIdx.x & 31;
    const __nv_bfloat16* xp = g_xb + (size_t)gw * DD;
    float xv[16];
    #pragma unroll
    for (int i = 0; i < 16; i++) xv[i] = __bfloat162float(xp[i * 32 + lane]);
    #pragma unroll
    for (int t = 0; t < NTAG; t++) {
        const float* wp = Wt + t * DD;
        float s = 0.f;
        #pragma unroll
        for (int i = 0; i < 16; i++) s += xv[i] * wp[i * 32 + lane];
        #pragma unroll
        for (int o = 16; o; o >>= 1) s += __shfl_xor_sync(0xffffffffu, s, o);
        if (lane == 0) g_em[(size_t)gw * NTAG + t] = s + bt[t];
    }
}

// ---------------- CRF: one warp per batch element ----------------
__global__ void crf_kernel(const float* __restrict__ trans, const int* __restrict__ tags) {
    int b    = blockIdx.x;
    int lane = threadIdx.x;
    __shared__ float trs[NTAG * NTAG];
    __shared__ float las[16];
    for (int i = lane; i < NTAG * NTAG; i += 32) trs[i] = trans[i];
    __syncwarp();

    const float* eb = g_em + (size_t)b * SS * NTAG;
    const int*   tg = tags + b * SS;

    float ts = 0.f;
    for (int s = lane; s < SS; s += 32) {
        int cur  = tg[s];
        int prev = (s == 0) ? START_TAG : tg[s - 1];
        ts += eb[s * NTAG + cur] + trs[prev * NTAG + cur];
    }
    #pragma unroll
    for (int o = 16; o; o >>= 1) ts += __shfl_xor_sync(0xffffffffu, ts, o);

    if (lane < NTAG) las[lane] = (lane == START_TAG) ? 0.f : -10000.f;
    __syncwarp();
    for (int s = 0; s < SS; s++) {
        float nla = -1e30f;
        if (lane < NTAG) {
            float m = -1e30f;
            #pragma unroll
            for (int i = 0; i < NTAG; i++) m = fmaxf(m, las[i] + trs[i * NTAG + lane]);
            float sme = 0.f;
            #pragma unroll
            for (int i = 0; i < NTAG; i++) sme += __expf(las[i] + trs[i * NTAG + lane] - m);
            nla = m + __logf(sme) + eb[s * NTAG + lane];
        }
        __syncwarp();
        if (lane < NTAG) las[lane] = nla;
        __syncwarp();
    }
    float v = (lane < NTAG) ? (las[lane] + trs[lane * NTAG + STOP_TAG]) : -1e30f;
    float m = v;
    #pragma unroll
    for (int o = 16; o; o >>= 1) m = fmaxf(m, __shfl_xor_sync(0xffffffffu, m, o));
    float sme = __expf(v - m);
    #pragma unroll
    for (int o = 16; o; o >>= 1) sme += __shfl_xor_sync(0xffffffffu, sme, o);
    if (lane == 0) {
        float logZ = m + __logf(sme);
        float last = trs[tg[SS - 1] * NTAG + STOP_TAG];
        g_loss[b] = logZ - (ts + last);
    }
}

__global__ void loss_reduce(float* __restrict__ out) {
    if (threadIdx.x == 0) {
        float s = 0.f;
        for (int i = 0; i < SB; i++) s += g_loss[i];
        out[0] = s * (1.f / SB);
    }
}

// ---------------- launch ----------------
extern "C" void kernel_launch(void* const* d_in, const int* in_sizes, int n_in,
                              void* d_out, int out_size) {
    const float* Wqkv  = (const float*)d_in[1];
    const float* bqkv  = (const float*)d_in[2];
    const float* Wo    = (const float*)d_in[3];
    const float* bo    = (const float*)d_in[4];
    const float* W1    = (const float*)d_in[5];
    const float* b1    = (const float*)d_in[6];
    const float* W2    = (const float*)d_in[7];
    const float* b2    = (const float*)d_in[8];
    const float* ln1g  = (const float*)d_in[9];
    const float* ln1b  = (const float*)d_in[10];
    const float* ln2g  = (const float*)d_in[11];
    const float* ln2b  = (const float*)d_in[12];
    const float* Wtag  = (const float*)d_in[13];
    const float* btag  = (const float*)d_in[14];
    const float* trans = (const float*)d_in[15];
    const int*   sent  = (const int*)d_in[16];
    const int*   tags  = (const int*)d_in[17];
    float* out = (float*)d_out;

    cudaFuncSetAttribute(attn_kernel, cudaFuncAttributeMaxDynamicSharedMemorySize, ATTN_SMEM);
    cudaFuncSetAttribute(mma_gemm<0>, cudaFuncAttributeMaxDynamicSharedMemorySize, GEMM_SMEM);
    cudaFuncSetAttribute(mma_gemm<1>, cudaFuncAttributeMaxDynamicSharedMemorySize, GEMM_SMEM);
    cudaFuncSetAttribute(mma_gemm<2>, cudaFuncAttributeMaxDynamicSharedMemorySize, GEMM_SMEM);
    cudaFuncSetAttribute(mma_gemm<3>, cudaFuncAttributeMaxDynamicSharedMemorySize, GEMM_SMEM);

    wconv_all<<<(WB_TOTAL / 2 + 255) / 256, 256>>>(Wqkv, Wo, W1, W2);
    pe_kernel<<<SS, DD / 2>>>();
    embed_kernel<<<NT, DD / 2>>>((const float*)d_in[0], sent);

    for (int l = 0; l < NL; l++) {
        mma_gemm<0><<<dim3(1536 / 128, NT / 128), 256, GEMM_SMEM>>>(
            OFF_QKV + (unsigned)l * 1536u * 512u, bqkv + (size_t)l * 1536);
        attn_kernel<<<SB * NH, 256, ATTN_SMEM>>>();
        mma_gemm<1><<<dim3(512 / 128, NT / 128), 256, GEMM_SMEM>>>(
            OFF_WO + (unsigned)l * 512u * 512u, bo + (size_t)l * 512);
        add_ln_kernel<<<NT / 8, 256>>>(ln1g + (size_t)l * DD, ln1b + (size_t)l * DD);
        mma_gemm<2><<<dim3(2048 / 128, NT / 128), 256, GEMM_SMEM>>>(
            OFF_W1 + (unsigned)l * 2048u * 512u, b1 + (size_t)l * 2048);
        mma_gemm<3><<<dim3(512 / 128, NT / 128), 256, GEMM_SMEM>>>(
            OFF_W2 + (unsigned)l * 512u * 2048u, b2 + (size_t)l * 512);
        add_ln_kernel<<<NT / 8, 256>>>(ln2g + (size_t)l * DD, ln2b + (size_t)l * DD);
    }

    emis_kernel<<<NT / 8, 256>>>(Wtag, btag);
    crf_kernel<<<SB, 32>>>(trans, tags);
    loss_reduce<<<1, 1>>>(out);
}